// round 14
// baseline (speedup 1.0000x reference)
#include <cuda_runtime.h>
#include <cub/cub.cuh>

// Problem constants (fixed by the reference setup_inputs)
constexpr int B  = 64;
constexpr int H  = 512;
constexpr int W  = 512;
constexpr int HW = H * W;        // 262144 = 2^18
constexpr int N  = B * HW;       // 16777216

// Per-batch sort: 64 groups x 1 batch. Key is just the 32-bit descending
// score mapping (no batch bits needed); val is the 18-bit pixel idx.
// Sorted position within a batch == final output row.
// Small per-pass grids (~30 blocks) let ~4 sort passes co-reside at cub's
// 1-block/SM occupancy — the R13 bottleneck was grid width, not streams.
constexpr int G   = 64;
constexpr int M   = N / G;         // 262144 elements per group (= HW)
constexpr size_t TEMP_PER = 4u << 20;

// 4 created streams: proven (R9/R11/R12) to leave device memory at baseline.
constexpr int S = 4;

// Static scratch (no allocation allowed)
__device__ unsigned g_keys_a[N];
__device__ unsigned g_keys_b[N];
__device__ unsigned g_vals_a[N];
__device__ unsigned g_vals_b[N];
__device__ float2   g_pairs[N];
__device__ unsigned char g_temp[G * TEMP_PER];

// ---------------------------------------------------------------------------
// Kernel 1 (per batch): 8-neighbor NMS + key encode + offset pairs.
//   key = descending-ordered score bits, val = idx (18 bits).
// Stable ascending sort of one batch == its final output order
// (score descending, idx-ascending ties).
// ---------------------------------------------------------------------------
__global__ void nms_encode_kernel(const float* __restrict__ hm,
                                  const float* __restrict__ off,
                                  unsigned* __restrict__ keys,
                                  unsigned* __restrict__ vals,
                                  float2* __restrict__ pairs,
                                  int b) {
    int idx = blockIdx.x * blockDim.x + threadIdx.x;
    if (idx >= HW) return;
    int y = idx >> 9;
    int x = idx & (W - 1);
    int g = b * HW + idx;

    const float* img = hm + (size_t)b * HW;
    float v = __ldg(img + idx);

    float m = -__int_as_float(0x7f800000);  // -inf
    if (y > 0) {
        const float* r = img + (y - 1) * W + x;
        if (x > 0)      m = fmaxf(m, __ldg(r - 1));
        m = fmaxf(m, __ldg(r));
        if (x < W - 1)  m = fmaxf(m, __ldg(r + 1));
    }
    {
        const float* r = img + y * W + x;
        if (x > 0)      m = fmaxf(m, __ldg(r - 1));
        if (x < W - 1)  m = fmaxf(m, __ldg(r + 1));
    }
    if (y < H - 1) {
        const float* r = img + (y + 1) * W + x;
        if (x > 0)      m = fmaxf(m, __ldg(r - 1));
        m = fmaxf(m, __ldg(r));
        if (x < W - 1)  m = fmaxf(m, __ldg(r + 1));
    }

    float jv = (m >= v) ? 0.6f * v : v;

    // float -> descending-ordered bits (jv >= 0 always)
    unsigned u = __float_as_uint(jv);
    keys[g] = ~(u ^ 0x80000000u);
    vals[g] = (unsigned)idx;

    const float* ob = off + (size_t)b * 2 * HW;
    float xo = __ldg(ob + idx);        // channel 0: x-offset
    float yo = __ldg(ob + HW + idx);   // channel 1: y-offset
    pairs[g] = make_float2(xo, yo);
}

// ---------------------------------------------------------------------------
// Kernel 2 (per batch): direct decode on the batch's stream.
// Sorted slot s within the batch -> output row b*HW + s.
// Coalesced key/val reads, L2-resident pair gathers, float4 writes.
// ---------------------------------------------------------------------------
__global__ void decode_kernel(const unsigned* __restrict__ ks,
                              const unsigned* __restrict__ vs,
                              const float2* __restrict__ pairs,
                              float* __restrict__ out,
                              int b) {
    int q = blockIdx.x * blockDim.x + threadIdx.x;   // quad index in batch
    if (q >= HW / 4) return;
    size_t p0 = (size_t)b * HW + (size_t)q * 4;      // global output row
    size_t q0 = ((size_t)b * HW) / 4 + (size_t)q;    // global quad index

    uint4 kq = ((const uint4*)ks)[q0];
    uint4 vq = ((const uint4*)vs)[q0];
    unsigned kk[4] = {kq.x, kq.y, kq.z, kq.w};
    unsigned vv[4] = {vq.x, vq.y, vq.z, vq.w};

    float r[12];
#pragma unroll
    for (int i = 0; i < 4; i++) {
        unsigned idx = vv[i];
        unsigned u   = (~kk[i]) ^ 0x80000000u;
        float score  = __uint_as_float(u);
        int y = (int)(idx >> 9), x = (int)(idx & (W - 1));

        float2 pr = __ldg(&pairs[((size_t)b << 18) | idx]);
        r[3 * i + 0] = (float)y + pr.y + 0.5f;   // y-offset
        r[3 * i + 1] = (float)x + pr.x + 0.5f;   // x-offset
        r[3 * i + 2] = score;
    }

    float4* o4 = (float4*)(out + p0 * 3);
    o4[0] = make_float4(r[0], r[1], r[2], r[3]);
    o4[1] = make_float4(r[4], r[5], r[6], r[7]);
    o4[2] = make_float4(r[8], r[9], r[10], r[11]);
}

extern "C" void kernel_launch(void* const* d_in, const int* in_sizes, int n_in,
                              void* d_out, int out_size) {
    const float* hm  = (const float*)d_in[0];
    const float* off = (const float*)d_in[1];
    float* out = (float*)d_out;

    unsigned *ka, *kb, *va, *vb;
    float2* pr;
    unsigned char* tmp;
    cudaGetSymbolAddress((void**)&ka, g_keys_a);
    cudaGetSymbolAddress((void**)&kb, g_keys_b);
    cudaGetSymbolAddress((void**)&va, g_vals_a);
    cudaGetSymbolAddress((void**)&vb, g_vals_b);
    cudaGetSymbolAddress((void**)&pr, g_pairs);
    cudaGetSymbolAddress((void**)&tmp, g_temp);

    // 4 created streams (memory-check proven), created and destroyed within
    // this call; graph replay never re-runs host code. Stream 0 carries no
    // work between fork and join (R13 showed it creates false ordering).
    cudaStream_t streams[S];
    cudaEvent_t ev_fork, ev_join[S];
    for (int s = 0; s < S; s++)
        cudaStreamCreateWithFlags(&streams[s], cudaStreamNonBlocking);
    cudaEventCreateWithFlags(&ev_fork, cudaEventDisableTiming);
    for (int s = 0; s < S; s++)
        cudaEventCreateWithFlags(&ev_join[s], cudaEventDisableTiming);

    cudaEventRecord(ev_fork, 0);
    for (int s = 0; s < S; s++)
        cudaStreamWaitEvent(streams[s], ev_fork, 0);

    const int gblocks = (HW + 255) / 256;
    const int dblocks = (HW / 4 + 255) / 256;
    for (int b = 0; b < G; b++) {
        cudaStream_t st = streams[b % S];

        // This batch's chain starts as soon as its slice is encoded,
        // overlapping other streams' encode/sort/decode work.
        nms_encode_kernel<<<gblocks, 256, 0, st>>>(hm, off, ka, va, pr, b);

        cub::DoubleBuffer<unsigned> dk(ka + (size_t)b * M, kb + (size_t)b * M);
        cub::DoubleBuffer<unsigned> dv(va + (size_t)b * M, vb + (size_t)b * M);
        size_t tb = TEMP_PER;
        cub::DeviceRadixSort::SortPairs(tmp + (size_t)b * TEMP_PER, tb,
                                        dk, dv, M, 0, 32, st);

        // Per-batch decode overlaps other batches' sorts; pass this batch's
        // own current buffers (base pointers, kernel indexes by batch).
        const unsigned* ksb = dk.Current() - (size_t)b * M;
        const unsigned* vsb = dv.Current() - (size_t)b * M;
        decode_kernel<<<dblocks, 256, 0, st>>>(ksb, vsb, pr, out, b);
    }

    // Join all side streams back into the capture stream.
    for (int s = 0; s < S; s++) {
        cudaEventRecord(ev_join[s], streams[s]);
        cudaStreamWaitEvent(0, ev_join[s], 0);
    }

    // Tear down capture-time objects (all side work joined into stream 0).
    for (int s = 0; s < S; s++) cudaStreamDestroy(streams[s]);
    cudaEventDestroy(ev_fork);
    for (int s = 0; s < S; s++) cudaEventDestroy(ev_join[s]);
}

// round 15
// speedup vs baseline: 1.9458x; 1.9458x over previous
#include <cuda_runtime.h>
#include <cub/cub.cuh>

// Problem constants (fixed by the reference setup_inputs)
constexpr int B  = 64;
constexpr int H  = 512;
constexpr int W  = 512;
constexpr int HW = H * W;        // 262144 = 2^18
constexpr int N  = B * HW;       // 16777216

// Value-bucketed counting sort: bucket = (2^18-1) - floor(jv * 2^18).
// Multiplication by 2^18 is EXACT in fp32 (exponent shift), so the bucket is
// a true floor and strictly monotone vs. the order key d (d1<d2 => b1<=b2).
// Payload (d<<18)|idx is a UNIQUE total-order key: per-bucket fixup sorting
// makes the result deterministic and exactly equal to the stable reference.
constexpr int KBITS = 18;
constexpr int KBUCK = 1 << KBITS;      // buckets per batch
constexpr int TOTB  = B * KBUCK;       // 16777216 buckets total

// Static scratch (no allocation allowed)
__device__ unsigned long long g_payload[N];   // (d<<18)|idx by input pos
__device__ unsigned long long g_sorted[N];    // scattered payloads
__device__ float2   g_pairs[N];               // interleaved (xo, yo)
__device__ unsigned g_hist[TOTB];             // per-(batch,bucket) counts
__device__ unsigned g_base[TOTB];             // global exclusive scan of hist
__device__ unsigned char g_temp[32 << 20];    // cub scan temp

// ---------------------------------------------------------------------------
// Kernel 1: 8-neighbor NMS + payload encode + value-bucket histogram +
// offset-pair interleave.
// ---------------------------------------------------------------------------
__global__ void nms_encode_kernel(const float* __restrict__ hm,
                                  const float* __restrict__ off,
                                  unsigned long long* __restrict__ payload,
                                  float2* __restrict__ pairs,
                                  unsigned* __restrict__ hist) {
    int g = blockIdx.x * blockDim.x + threadIdx.x;
    if (g >= N) return;
    int idx = g & (HW - 1);
    int b   = g >> 18;
    int y   = idx >> 9;
    int x   = idx & (W - 1);

    const float* img = hm + (size_t)b * HW;
    float v = __ldg(img + idx);

    float m = -__int_as_float(0x7f800000);  // -inf
    if (y > 0) {
        const float* r = img + (y - 1) * W + x;
        if (x > 0)      m = fmaxf(m, __ldg(r - 1));
        m = fmaxf(m, __ldg(r));
        if (x < W - 1)  m = fmaxf(m, __ldg(r + 1));
    }
    {
        const float* r = img + y * W + x;
        if (x > 0)      m = fmaxf(m, __ldg(r - 1));
        if (x < W - 1)  m = fmaxf(m, __ldg(r + 1));
    }
    if (y < H - 1) {
        const float* r = img + (y + 1) * W + x;
        if (x > 0)      m = fmaxf(m, __ldg(r - 1));
        m = fmaxf(m, __ldg(r));
        if (x < W - 1)  m = fmaxf(m, __ldg(r + 1));
    }

    float jv = (m >= v) ? 0.6f * v : v;

    // d: ascending d == descending score (jv >= 0 always)
    unsigned u = __float_as_uint(jv);
    unsigned d = ~(u ^ 0x80000000u);
    payload[g] = ((unsigned long long)d << 18) | (unsigned)idx;

    // value bucket, monotone with d (jv in [0,1) => product < 2^18, exact)
    unsigned bucket = (KBUCK - 1) - (unsigned)(jv * 262144.0f);
    atomicAdd(&hist[((unsigned)b << KBITS) | bucket], 1u);

    const float* ob = off + (size_t)b * 2 * HW;
    float xo = __ldg(ob + idx);        // channel 0: x-offset
    float yo = __ldg(ob + HW + idx);   // channel 1: y-offset
    pairs[g] = make_float2(xo, yo);
}

// ---------------------------------------------------------------------------
// Kernel 2: scatter payloads to bucket positions. Global scan already
// includes b*HW (batch totals are exactly HW), so pos is the global slot.
// Order within a bucket is arbitrary here; fixup sorts it.
// ---------------------------------------------------------------------------
__global__ void scatter_kernel(const unsigned long long* __restrict__ payload,
                               unsigned* __restrict__ base,
                               unsigned long long* __restrict__ sorted) {
    int g = blockIdx.x * blockDim.x + threadIdx.x;
    if (g >= N) return;
    unsigned long long p = payload[g];
    unsigned d  = (unsigned)(p >> 18);
    float jv    = __uint_as_float((~d) ^ 0x80000000u);
    unsigned bucket = (KBUCK - 1) - (unsigned)(jv * 262144.0f);
    unsigned b  = (unsigned)(g >> 18);
    unsigned pos = atomicAdd(&base[(b << KBITS) | bucket], 1u);
    sorted[pos] = p;
}

// ---------------------------------------------------------------------------
// Kernel 3: per-bucket fixup. base (post-scatter) = start + L, so
// start = base - L with no extra array. Sort payload ascending = exact
// reference order (score desc, idx asc). Capped fast path + always-correct
// global-memory fallback for improbably long runs.
// ---------------------------------------------------------------------------
__global__ void fixup_kernel(const unsigned* __restrict__ hist,
                             const unsigned* __restrict__ base,
                             unsigned long long* __restrict__ sorted) {
    int s = blockIdx.x * blockDim.x + threadIdx.x;
    if (s >= TOTB) return;
    unsigned L = hist[s];
    if (L < 2) return;
    unsigned start = base[s] - L;
    if (L <= 24) {
        unsigned long long v[24];
        for (unsigned i = 0; i < L; i++) v[i] = sorted[start + i];
        for (unsigned i = 1; i < L; i++) {
            unsigned long long key = v[i];
            int j = (int)i - 1;
            while (j >= 0 && v[j] > key) { v[j + 1] = v[j]; j--; }
            v[j + 1] = key;
        }
        for (unsigned i = 0; i < L; i++) sorted[start + i] = v[i];
    } else {
        for (unsigned i = 1; i < L; i++) {
            unsigned long long key = sorted[start + i];
            long j = (long)i - 1;
            while (j >= 0 && sorted[start + j] > key) {
                sorted[start + j + 1] = sorted[start + j];
                j--;
            }
            sorted[start + j + 1] = key;
        }
    }
}

// ---------------------------------------------------------------------------
// Kernel 4: linear decode. Output row == sorted slot; batch = slot >> 18.
// Coalesced payload reads, L2-friendly pair gathers, float4 writes.
// ---------------------------------------------------------------------------
__global__ void decode_kernel(const unsigned long long* __restrict__ sorted,
                              const float2* __restrict__ pairs,
                              float* __restrict__ out) {
    int q = blockIdx.x * blockDim.x + threadIdx.x;   // quad index
    if (q >= N / 4) return;
    size_t p0 = (size_t)q * 4;

    float r[12];
#pragma unroll
    for (int i = 0; i < 4; i++) {
        size_t p = p0 + i;
        unsigned long long pl = sorted[p];
        unsigned idx = (unsigned)(pl & 0x3FFFFull);
        unsigned d   = (unsigned)(pl >> 18);
        float score  = __uint_as_float((~d) ^ 0x80000000u);
        unsigned b   = (unsigned)(p >> 18);
        int y = (int)(idx >> 9), x = (int)(idx & (W - 1));

        float2 pr = __ldg(&pairs[((size_t)b << 18) | idx]);
        r[3 * i + 0] = (float)y + pr.y + 0.5f;   // y-offset
        r[3 * i + 1] = (float)x + pr.x + 0.5f;   // x-offset
        r[3 * i + 2] = score;
    }

    float4* o4 = (float4*)(out + p0 * 3);
    o4[0] = make_float4(r[0], r[1], r[2], r[3]);
    o4[1] = make_float4(r[4], r[5], r[6], r[7]);
    o4[2] = make_float4(r[8], r[9], r[10], r[11]);
}

extern "C" void kernel_launch(void* const* d_in, const int* in_sizes, int n_in,
                              void* d_out, int out_size) {
    const float* hm  = (const float*)d_in[0];
    const float* off = (const float*)d_in[1];
    float* out = (float*)d_out;

    unsigned long long *pl, *so;
    float2* pr;
    unsigned *hi, *ba;
    unsigned char* tmp;
    cudaGetSymbolAddress((void**)&pl, g_payload);
    cudaGetSymbolAddress((void**)&so, g_sorted);
    cudaGetSymbolAddress((void**)&pr, g_pairs);
    cudaGetSymbolAddress((void**)&hi, g_hist);
    cudaGetSymbolAddress((void**)&ba, g_base);
    cudaGetSymbolAddress((void**)&tmp, g_temp);

    // 1. zero histogram (graph-capturable, replay-safe)
    cudaMemsetAsync(hi, 0, (size_t)TOTB * sizeof(unsigned), 0);

    const int blocks = (N + 255) / 256;

    // 2. NMS + payload + value-bucket histogram + pair interleave
    nms_encode_kernel<<<blocks, 256>>>(hm, off, pl, pr, hi);

    // 3. ONE global exclusive scan: global prefix == b*HW + in-batch offset
    size_t tb = sizeof(g_temp);
    cub::DeviceScan::ExclusiveSum(tmp, tb, hi, ba, TOTB, 0);

    // 4. bucket scatter (base becomes start+L per bucket afterwards)
    scatter_kernel<<<blocks, 256>>>(pl, ba, so);

    // 5. per-bucket fixup -> exact deterministic reference order
    fixup_kernel<<<(TOTB + 255) / 256, 256>>>(hi, ba, so);

    // 6. decode to final rows
    decode_kernel<<<(N / 4 + 255) / 256, 256>>>(so, pr, out);
}